// round 2
// baseline (speedup 1.0000x reference)
#include <cuda_runtime.h>
#include <cuda_bf16.h>

#define NB   4
#define LF   256
#define LS   128
#define NC   8
#define NN   512
#define TOT  (NC*LF*NN*16)

__device__ __align__(16) float g_sc[TOT];
__device__ __align__(16) float g_dt[TOT];
__device__ __align__(16) float g_zg[TOT];
__device__ __align__(16) float g_B [TOT];
__device__ __align__(16) float g_C [TOT];
__device__ __align__(16) float g_yf[TOT];
__device__ __align__(16) float g_part[NC*16*NN*8];

// ---------------- FFMA-only transcendentals ----------------
__device__ __forceinline__ float fexp(float x) {
    x = fmaxf(-87.0f, fminf(87.0f, x));
    const float L2E = 1.4426950408889634f;
    float r = rintf(x * L2E);
    float u = fmaf(x, L2E, -r) * 0.6931471805599453f;
    float p = 1.9841270e-4f;
    p = fmaf(p, u, 1.3888889e-3f);
    p = fmaf(p, u, 8.3333333e-3f);
    p = fmaf(p, u, 4.1666667e-2f);
    p = fmaf(p, u, 1.6666667e-1f);
    p = fmaf(p, u, 0.5f);
    p = fmaf(p, u, 1.0f);
    p = fmaf(p, u, 1.0f);
    return __int_as_float(((int)r + 127) << 23) * p;
}
__device__ __forceinline__ float rcp12(float d) {  // 1/d, d in [1,2]
    float y = fmaf(d, -0.47058824f, 1.4117647f);
    float t = fmaf(-d, y, 1.0f); y = fmaf(y, t, y);
    t = fmaf(-d, y, 1.0f);       y = fmaf(y, t, y);
    return y;
}
__device__ __forceinline__ float fsig(float x) {
    float a = fabsf(x);
    float e = fexp(-a);
    float r = rcp12(1.0f + e);
    return (x >= 0.0f) ? r : e * r;
}
__device__ __forceinline__ float fsoftplus(float v) {
    float a  = fabsf(v);
    float e  = fexp(-a);
    float w  = e * (0.5f * rcp12(fmaf(0.5f, e, 1.0f)));    // e/(2+e) in (0,1/3]
    float w2 = w * w;
    float poly = fmaf(w2, fmaf(w2, fmaf(w2, 0.14285714f, 0.2f), 0.33333333f), 1.0f);
    return fmaxf(v, 0.0f) + 2.0f * w * poly;                // max(v,0)+2atanh(w)
}
__device__ __forceinline__ float dot16(const float* sc, const float4* r4) {
    float4 a = r4[0], b = r4[1], c = r4[2], d = r4[3];
    float r = sc[0]*a.x;
    r = fmaf(sc[1], a.y, r);  r = fmaf(sc[2], a.z, r);  r = fmaf(sc[3], a.w, r);
    r = fmaf(sc[4], b.x, r);  r = fmaf(sc[5], b.y, r);  r = fmaf(sc[6], b.z, r);  r = fmaf(sc[7], b.w, r);
    r = fmaf(sc[8], c.x, r);  r = fmaf(sc[9], c.y, r);  r = fmaf(sc[10],c.z, r);  r = fmaf(sc[11],c.w, r);
    r = fmaf(sc[12],d.x, r);  r = fmaf(sc[13],d.y, r);  r = fmaf(sc[14],d.z, r);  r = fmaf(sc[15],d.w, r);
    return r;
}

// ========== Kernel A: lift+in_proj (folded) + conv + silu + x_proj + dt ==========
// grid (512 n, 8 c), block 256 (t)
__global__ void __launch_bounds__(256) kA(
    const float* __restrict__ x,     const float* __restrict__ lift_w,
    const float* __restrict__ lift_b,const float* __restrict__ ipw,
    const float* __restrict__ conv_w,const float* __restrict__ conv_b,
    const float* __restrict__ xpw,   const float* __restrict__ dt_w,
    const float* __restrict__ dt_b)
{
    __shared__ float x_sh[LF + 4];
    __shared__ float s_w1[32], s_b1[32], s_cw[64], s_cb[16], s_dtw[16], s_dtb[16];
    __shared__ float4 s_xpw4[132];   // 33 rows x 16

    const int t = threadIdx.x, n = blockIdx.x, c = blockIdx.y;
    const int b = n >> 7, ls = n & 127;

    float* sx = (float*)s_xpw4;
    for (int i = t; i < 528; i += 256) sx[i] = xpw[c*528 + i];
    if (t < 32) {
        float w = 0.f, bs = 0.f;
        #pragma unroll
        for (int d = 0; d < 8; ++d) {
            float ip = ipw[(c*32 + t)*8 + d];
            w  = fmaf(lift_w[c*8 + d], ip, w);
            bs = fmaf(lift_b[c*8 + d], ip, bs);
        }
        s_w1[t] = w; s_b1[t] = bs;
    } else if (t < 96)  s_cw [t-32]  = conv_w[c*64 + (t-32)];
    else if (t < 112)   s_cb [t-96]  = conv_b[c*16 + (t-96)];
    else if (t < 128)   s_dtw[t-112] = dt_w  [c*16 + (t-112)];
    else if (t < 144)   s_dtb[t-128] = dt_b  [c*16 + (t-128)];
    x_sh[3 + t] = x[((b*LF + t)*LS + ls)*NC + c];
    if (t < 3) x_sh[t] = 0.f;
    __syncthreads();

    const float xv0 = x_sh[t], xv1 = x_sh[t+1], xv2 = x_sh[t+2], xv3 = x_sh[t+3];
    const float m0 = (t >= 3) ? 1.f : 0.f;
    const float m1 = (t >= 2) ? 1.f : 0.f;
    const float m2 = (t >= 1) ? 1.f : 0.f;

    const int o = ((c*LF + t)*NN + n)*16;

    float sc[16];
    #pragma unroll
    for (int di = 0; di < 16; ++di) {
        float w = s_w1[di], bs = s_b1[di];
        float acc = s_cb[di];
        acc = fmaf(m0 * fmaf(xv0, w, bs), s_cw[di*4+0], acc);
        acc = fmaf(m1 * fmaf(xv1, w, bs), s_cw[di*4+1], acc);
        acc = fmaf(m2 * fmaf(xv2, w, bs), s_cw[di*4+2], acc);
        acc = fmaf(     fmaf(xv3, w, bs), s_cw[di*4+3], acc);
        sc[di] = acc * fsig(acc);
    }
    float4* gsc = reinterpret_cast<float4*>(g_sc);
    float4* gzg = reinterpret_cast<float4*>(g_zg);
    float4* gB  = reinterpret_cast<float4*>(g_B);
    float4* gC  = reinterpret_cast<float4*>(g_C);
    float4* gdt = reinterpret_cast<float4*>(g_dt);
    #pragma unroll
    for (int q = 0; q < 4; ++q)
        gsc[(o>>2)+q] = make_float4(sc[4*q], sc[4*q+1], sc[4*q+2], sc[4*q+3]);
    #pragma unroll
    for (int q = 0; q < 4; ++q) {
        float zs[4];
        #pragma unroll
        for (int e = 0; e < 4; ++e) {
            int di = 4*q + e;
            float zv = fmaf(xv3, s_w1[16+di], s_b1[16+di]);
            zs[e] = zv * fsig(zv);
        }
        gzg[(o>>2)+q] = make_float4(zs[0], zs[1], zs[2], zs[3]);
    }
    const float dtlo = dot16(sc, s_xpw4);
    #pragma unroll
    for (int q = 0; q < 4; ++q) {
        float v[4];
        #pragma unroll
        for (int e = 0; e < 4; ++e) v[e] = dot16(sc, s_xpw4 + 4*(1 + 4*q + e));
        gB[(o>>2)+q] = make_float4(v[0], v[1], v[2], v[3]);
    }
    #pragma unroll
    for (int q = 0; q < 4; ++q) {
        float v[4];
        #pragma unroll
        for (int e = 0; e < 4; ++e) v[e] = dot16(sc, s_xpw4 + 4*(17 + 4*q + e));
        gC[(o>>2)+q] = make_float4(v[0], v[1], v[2], v[3]);
    }
    #pragma unroll
    for (int q = 0; q < 4; ++q) {
        float v[4];
        #pragma unroll
        for (int e = 0; e < 4; ++e)
            v[e] = fsoftplus(fmaf(dtlo, s_dtw[4*q+e], s_dtb[4*q+e]));
        gdt[(o>>2)+q] = make_float4(v[0], v[1], v[2], v[3]);
    }
}

// ========== Kernel B: selective scan, thread = (c,n,di) lane with h[16] ==========
__global__ void __launch_bounds__(256) kB(
    const float* __restrict__ A_log, const float* __restrict__ D_skip)
{
    const int id = blockIdx.x*256 + threadIdx.x;
    const int di = id & 15;
    const int n  = (id >> 4) & 511;
    const int c  = id >> 13;

    float A[16];
    #pragma unroll
    for (int s = 0; s < 16; ++s) A[s] = -__expf(__ldg(&A_log[(c*16 + di)*16 + s]));
    bool st = true;
    #pragma unroll
    for (int s = 1; s < 16; ++s) {
        float tgt = A[0] * (float)(s + 1);
        st = st && (fabsf(A[s] - tgt) <= 1e-4f * fabsf(tgt));
    }
    const float Dsk = __ldg(&D_skip[c*16 + di]);

    float h[16];
    #pragma unroll
    for (int s = 0; s < 16; ++s) h[s] = 0.f;

    const float4* B4 = reinterpret_cast<const float4*>(g_B);
    const float4* C4 = reinterpret_cast<const float4*>(g_C);
    const int orow = (c*LF*NN + n)*16;
    const int tstride = NN*16;

    if (st) {
        #pragma unroll 2
        for (int t = 0; t < LF; ++t) {
            int o = orow + t*tstride;
            float dtv = __ldg(&g_dt[o + di]);
            float scv = __ldg(&g_sc[o + di]);
            float zgv = __ldg(&g_zg[o + di]);
            float4 q0 = __ldg(&B4[(o>>2)+0]), q1 = __ldg(&B4[(o>>2)+1]);
            float4 q2 = __ldg(&B4[(o>>2)+2]), q3 = __ldg(&B4[(o>>2)+3]);
            float4 r0 = __ldg(&C4[(o>>2)+0]), r1 = __ldg(&C4[(o>>2)+1]);
            float4 r2 = __ldg(&C4[(o>>2)+2]), r3 = __ldg(&C4[(o>>2)+3]);
            float Bv[16] = {q0.x,q0.y,q0.z,q0.w, q1.x,q1.y,q1.z,q1.w,
                            q2.x,q2.y,q2.z,q2.w, q3.x,q3.y,q3.z,q3.w};
            float Cv[16] = {r0.x,r0.y,r0.z,r0.w, r1.x,r1.y,r1.z,r1.w,
                            r2.x,r2.y,r2.z,r2.w, r3.x,r3.y,r3.z,r3.w};
            float u  = dtv * scv;
            float e1 = fexp(dtv * A[0]);
            float p[16];
            p[0]=e1;        p[1]=p[0]*p[0];  p[2]=p[1]*p[0];  p[3]=p[1]*p[1];
            p[4]=p[3]*p[0]; p[5]=p[3]*p[1];  p[6]=p[3]*p[2];  p[7]=p[3]*p[3];
            p[8]=p[7]*p[0]; p[9]=p[7]*p[1];  p[10]=p[7]*p[2]; p[11]=p[7]*p[3];
            p[12]=p[7]*p[4];p[13]=p[7]*p[5]; p[14]=p[7]*p[6]; p[15]=p[7]*p[7];
            float y = 0.f;
            #pragma unroll
            for (int s = 0; s < 16; ++s) {
                h[s] = fmaf(p[s], h[s], u * Bv[s]);
                y = fmaf(h[s], Cv[s], y);
            }
            g_yf[o + di] = (y + Dsk * scv) * zgv;
        }
    } else {
        #pragma unroll 1
        for (int t = 0; t < LF; ++t) {
            int o = orow + t*tstride;
            float dtv = __ldg(&g_dt[o + di]);
            float scv = __ldg(&g_sc[o + di]);
            float zgv = __ldg(&g_zg[o + di]);
            float4 q0 = __ldg(&B4[(o>>2)+0]), q1 = __ldg(&B4[(o>>2)+1]);
            float4 q2 = __ldg(&B4[(o>>2)+2]), q3 = __ldg(&B4[(o>>2)+3]);
            float4 r0 = __ldg(&C4[(o>>2)+0]), r1 = __ldg(&C4[(o>>2)+1]);
            float4 r2 = __ldg(&C4[(o>>2)+2]), r3 = __ldg(&C4[(o>>2)+3]);
            float Bv[16] = {q0.x,q0.y,q0.z,q0.w, q1.x,q1.y,q1.z,q1.w,
                            q2.x,q2.y,q2.z,q2.w, q3.x,q3.y,q3.z,q3.w};
            float Cv[16] = {r0.x,r0.y,r0.z,r0.w, r1.x,r1.y,r1.z,r1.w,
                            r2.x,r2.y,r2.z,r2.w, r3.x,r3.y,r3.z,r3.w};
            float u = dtv * scv;
            float y = 0.f;
            #pragma unroll
            for (int s = 0; s < 16; ++s) {
                float P = fexp(dtv * A[s]);
                h[s] = fmaf(P, h[s], u * Bv[s]);
                y = fmaf(h[s], Cv[s], y);
            }
            g_yf[o + di] = (y + Dsk * scv) * zgv;
        }
    }
}

// ========== Kernel C: folded out_proj∘blk + partial time-pooling ==========
// thread = (c, chunk of 16 t's, n); M = blk_w @ out_w folded in shared
__global__ void __launch_bounds__(256) kC(
    const float* __restrict__ out_w, const float* __restrict__ blk_w,
    const float* __restrict__ blk_b)
{
    const int id = blockIdx.x*256 + threadIdx.x;
    const int n = id & 511, chunk = (id >> 9) & 15, c = id >> 13;
    const int tid = threadIdx.x;

    __shared__ float s_M[8][16];
    __shared__ float s_bb[8];
    if (tid < 128) {
        int d = tid >> 4, i = tid & 15;
        float m = 0.f;
        #pragma unroll
        for (int e = 0; e < 8; ++e)
            m = fmaf(blk_w[(c*8+d)*8+e], out_w[(c*8+e)*16+i], m);
        s_M[d][i] = m;
        if (i == 0) s_bb[d] = blk_b[c*8+d];
    }
    __syncthreads();

    float acc[8] = {0,0,0,0,0,0,0,0};
    const float4* Y4 = reinterpret_cast<const float4*>(g_yf);
    #pragma unroll 2
    for (int tt = 0; tt < 16; ++tt) {
        int t = chunk*16 + tt;
        int o = ((c*LF + t)*NN + n)*16;
        float4 a = __ldg(&Y4[(o>>2)+0]), b = __ldg(&Y4[(o>>2)+1]);
        float4 cc = __ldg(&Y4[(o>>2)+2]), dd = __ldg(&Y4[(o>>2)+3]);
        float y[16] = {a.x,a.y,a.z,a.w, b.x,b.y,b.z,b.w,
                       cc.x,cc.y,cc.z,cc.w, dd.x,dd.y,dd.z,dd.w};
        #pragma unroll
        for (int d = 0; d < 8; ++d) {
            float v = s_bb[d];
            #pragma unroll
            for (int i = 0; i < 16; ++i) v = fmaf(y[i], s_M[d][i], v);
            acc[d] += v * fsig(v);
        }
    }
    #pragma unroll
    for (int d = 0; d < 8; ++d)
        g_part[((c*16 + chunk)*NN + n)*8 + d] = acc[d];
}

// ========== Kernel D: final pooling + LayerNorm(64) ==========
__global__ void __launch_bounds__(64) kD(
    const float* __restrict__ ln_g, const float* __restrict__ ln_b,
    float* __restrict__ out)
{
    const int n = blockIdx.x, f = threadIdx.x;
    const int c = f >> 3, d = f & 7;
    float s = 0.f;
    #pragma unroll
    for (int ch = 0; ch < 16; ++ch)
        s += g_part[((c*16 + ch)*NN + n)*8 + d];
    float feat = s * (1.0f/256.0f);

    __shared__ float buf[64];
    buf[f] = feat;
    __syncthreads();
    float s1 = 0.f, s2 = 0.f;
    #pragma unroll
    for (int i = 0; i < 64; ++i) { float v = buf[i]; s1 += v; s2 = fmaf(v, v, s2); }
    float mu  = s1 * (1.0f/64.0f);
    float var = fmaxf(s2 * (1.0f/64.0f) - mu*mu, 0.f);
    float inv = rsqrtf(var + 1e-5f);
    out[n*64 + f] = (feat - mu) * inv * ln_g[f] + ln_b[f];
}

extern "C" void kernel_launch(void* const* d_in, const int* in_sizes, int n_in,
                              void* d_out, int out_size) {
    const float* x      = (const float*)d_in[0];
    const float* lift_w = (const float*)d_in[1];
    const float* lift_b = (const float*)d_in[2];
    const float* ipw    = (const float*)d_in[3];
    const float* conv_w = (const float*)d_in[4];
    const float* conv_b = (const float*)d_in[5];
    const float* xpw    = (const float*)d_in[6];
    const float* dt_w   = (const float*)d_in[7];
    const float* dt_b   = (const float*)d_in[8];
    const float* A_log  = (const float*)d_in[9];
    const float* D_skip = (const float*)d_in[10];
    const float* out_w  = (const float*)d_in[11];
    const float* blk_w  = (const float*)d_in[12];
    const float* blk_b  = (const float*)d_in[13];
    const float* ln_g   = (const float*)d_in[14];
    const float* ln_b   = (const float*)d_in[15];
    float* out = (float*)d_out;

    kA<<<dim3(NN, NC), 256>>>(x, lift_w, lift_b, ipw, conv_w, conv_b, xpw, dt_w, dt_b);
    kB<<<256, 256>>>(A_log, D_skip);
    kC<<<256, 256>>>(out_w, blk_w, blk_b);
    kD<<<NN, 64>>>(ln_g, ln_b, out);
}

// round 5
// speedup vs baseline: 1.1836x; 1.1836x over previous
#include <cuda_runtime.h>
#include <cuda_bf16.h>

#define NB   4
#define LF   256
#define LS   128
#define NC   8
#define NN   512
#define TOT  (NC*LF*NN*16)

__device__ __align__(16) float g_sc[TOT];
__device__ __align__(16) float g_dt[TOT];
__device__ __align__(16) float g_zg[TOT];
__device__ __align__(16) float g_B [TOT];
__device__ __align__(16) float g_C [TOT];
__device__ __align__(16) float g_yf[TOT];
__device__ __align__(16) float g_part[NC*16*NN*8];

// ---------------- MUFU-based transcendentals (off the FMA pipe) ----------------
__device__ __forceinline__ float fsig(float x) {
    float e = __expf(-fabsf(x));
    float r = __frcp_rn(1.0f + e);
    return (x >= 0.0f) ? r : e * r;
}
__device__ __forceinline__ float fsilu(float x) { return x * fsig(x); }
__device__ __forceinline__ float fsoftplus(float v) {
    float e = __expf(-fabsf(v));
    return fmaxf(v, 0.0f) + __logf(1.0f + e);
}
__device__ __forceinline__ float dot16s(const float* sc, const float* w) {
    float r = sc[0] * w[0];
    #pragma unroll
    for (int i = 1; i < 16; ++i) r = fmaf(sc[i], w[i], r);
    return r;
}

// ========== Kernel A: lift+in_proj (folded) + conv + silu + x_proj + dt ==========
// grid (t=256, c=8), block 256 threads = n; coalesced scratch stores
__global__ void __launch_bounds__(256) kA(
    const float* __restrict__ x,     const float* __restrict__ lift_w,
    const float* __restrict__ lift_b,const float* __restrict__ ipw,
    const float* __restrict__ conv_w,const float* __restrict__ conv_b,
    const float* __restrict__ xpw,   const float* __restrict__ dt_w,
    const float* __restrict__ dt_b)
{
    __shared__ float s_xpw[528];
    __shared__ float s_w1[32], s_b1[32], s_cw[64], s_cb[16], s_dtw[16], s_dtb[16];

    const int tid = threadIdx.x, t = blockIdx.x, c = blockIdx.y;

    for (int i = tid; i < 528; i += 256) s_xpw[i] = xpw[c*528 + i];
    if (tid < 32) {
        float w = 0.f, bs = 0.f;
        #pragma unroll
        for (int d = 0; d < 8; ++d) {
            float ip = ipw[(c*32 + tid)*8 + d];
            w  = fmaf(lift_w[c*8 + d], ip, w);
            bs = fmaf(lift_b[c*8 + d], ip, bs);
        }
        s_w1[tid] = w; s_b1[tid] = bs;
    } else if (tid < 96)  s_cw [tid-32]  = conv_w[c*64 + (tid-32)];
    else if (tid < 112)   s_cb [tid-96]  = conv_b[c*16 + (tid-96)];
    else if (tid < 128)   s_dtw[tid-112] = dt_w  [c*16 + (tid-112)];
    else if (tid < 144)   s_dtb[tid-128] = dt_b  [c*16 + (tid-128)];
    __syncthreads();

    const float m0 = (t >= 3) ? 1.f : 0.f;
    const float m1 = (t >= 2) ? 1.f : 0.f;
    const float m2 = (t >= 1) ? 1.f : 0.f;

    #pragma unroll
    for (int half = 0; half < 2; ++half) {
        const int n = tid + half*256;
        const int b = n >> 7, ls = n & 127;
        const float* xb = x + ((size_t)b*LF*LS + ls)*NC + c;
        const float xv0 = (t >= 3) ? __ldg(xb + (size_t)(t-3)*(LS*NC)) : 0.f;
        const float xv1 = (t >= 2) ? __ldg(xb + (size_t)(t-2)*(LS*NC)) : 0.f;
        const float xv2 = (t >= 1) ? __ldg(xb + (size_t)(t-1)*(LS*NC)) : 0.f;
        const float xv3 =            __ldg(xb + (size_t)t*(LS*NC));

        float sc[16];
        #pragma unroll
        for (int di = 0; di < 16; ++di) {
            float w = s_w1[di], bs = s_b1[di];
            float acc = s_cb[di];
            acc = fmaf(m0 * fmaf(xv0, w, bs), s_cw[di*4+0], acc);
            acc = fmaf(m1 * fmaf(xv1, w, bs), s_cw[di*4+1], acc);
            acc = fmaf(m2 * fmaf(xv2, w, bs), s_cw[di*4+2], acc);
            acc = fmaf(     fmaf(xv3, w, bs), s_cw[di*4+3], acc);
            sc[di] = fsilu(acc);
        }

        const int o = ((c*LF + t)*NN + n)*16;
        float4* gsc = reinterpret_cast<float4*>(g_sc);
        float4* gzg = reinterpret_cast<float4*>(g_zg);
        float4* gB  = reinterpret_cast<float4*>(g_B);
        float4* gC  = reinterpret_cast<float4*>(g_C);
        float4* gdt = reinterpret_cast<float4*>(g_dt);

        #pragma unroll
        for (int q = 0; q < 4; ++q)
            gsc[(o>>2)+q] = make_float4(sc[4*q], sc[4*q+1], sc[4*q+2], sc[4*q+3]);

        #pragma unroll
        for (int q = 0; q < 4; ++q) {
            float zs[4];
            #pragma unroll
            for (int e = 0; e < 4; ++e) {
                int di = 4*q + e;
                zs[e] = fsilu(fmaf(xv3, s_w1[16+di], s_b1[16+di]));
            }
            gzg[(o>>2)+q] = make_float4(zs[0], zs[1], zs[2], zs[3]);
        }

        const float dtlo = dot16s(sc, s_xpw);
        #pragma unroll
        for (int q = 0; q < 4; ++q) {
            float v[4];
            #pragma unroll
            for (int e = 0; e < 4; ++e) v[e] = dot16s(sc, s_xpw + (1 + 4*q + e)*16);
            gB[(o>>2)+q] = make_float4(v[0], v[1], v[2], v[3]);
        }
        #pragma unroll
        for (int q = 0; q < 4; ++q) {
            float v[4];
            #pragma unroll
            for (int e = 0; e < 4; ++e) v[e] = dot16s(sc, s_xpw + (17 + 4*q + e)*16);
            gC[(o>>2)+q] = make_float4(v[0], v[1], v[2], v[3]);
        }
        #pragma unroll
        for (int q = 0; q < 4; ++q) {
            float v[4];
            #pragma unroll
            for (int e = 0; e < 4; ++e)
                v[e] = fsoftplus(fmaf(dtlo, s_dtw[4*q+e], s_dtb[4*q+e]));
            gdt[(o>>2)+q] = make_float4(v[0], v[1], v[2], v[3]);
        }
    }
}

// ========== Kernel B: selective scan, thread = (c,n,di,sq) with h[4] ==========
// 262144 threads; y reduced across the 4 s-quads via shfl
__global__ void __launch_bounds__(256) kB(
    const float* __restrict__ A_log, const float* __restrict__ D_skip)
{
    const int id = blockIdx.x*256 + threadIdx.x;
    const int sq = id & 3;
    const int di = (id >> 2) & 15;
    const int n  = (id >> 6) & 511;
    const int c  = id >> 15;

    const float A0 = -__expf(__ldg(&A_log[(c*16 + di)*16]));
    float A[4];
    bool st = true;
    #pragma unroll
    for (int r = 0; r < 4; ++r) {
        A[r] = -__expf(__ldg(&A_log[(c*16 + di)*16 + 4*sq + r]));
        float tgt = A0 * (float)(4*sq + r + 1);
        st = st && (fabsf(A[r] - tgt) <= 1e-4f * fabsf(tgt));
    }
    st = __all_sync(0xffffffffu, st);
    const float Dsk = __ldg(&D_skip[c*16 + di]);

    float h0 = 0.f, h1 = 0.f, h2 = 0.f, h3 = 0.f;
    const int orow = (c*LF*NN + n)*16;
    const float4* B4 = reinterpret_cast<const float4*>(g_B);
    const float4* C4 = reinterpret_cast<const float4*>(g_C);

    if (st) {
        #pragma unroll 4
        for (int t = 0; t < LF; ++t) {
            const int o = orow + t*(NN*16);
            float dtv = __ldg(&g_dt[o + di]);
            float scv = __ldg(&g_sc[o + di]);
            float zgv = __ldg(&g_zg[o + di]);
            float4 Bq = __ldg(&B4[(o>>2) + sq]);
            float4 Cq = __ldg(&C4[(o>>2) + sq]);
            float e1 = __expf(dtv * A0);
            float e2 = e1*e1, e3 = e2*e1, e4 = e2*e2, e8 = e4*e4;
            float base = (sq == 0) ? 1.f : (sq == 1) ? e4 : (sq == 2) ? e8 : e8*e4;
            float u = dtv * scv;
            h0 = fmaf(base*e1, h0, u*Bq.x);
            h1 = fmaf(base*e2, h1, u*Bq.y);
            h2 = fmaf(base*e3, h2, u*Bq.z);
            h3 = fmaf(base*e4, h3, u*Bq.w);
            float y = h0*Cq.x;
            y = fmaf(h1, Cq.y, y); y = fmaf(h2, Cq.z, y); y = fmaf(h3, Cq.w, y);
            y += __shfl_xor_sync(0xffffffffu, y, 1);
            y += __shfl_xor_sync(0xffffffffu, y, 2);
            if (sq == 0) g_yf[o + di] = fmaf(Dsk, scv, y) * zgv;
        }
    } else {
        #pragma unroll 2
        for (int t = 0; t < LF; ++t) {
            const int o = orow + t*(NN*16);
            float dtv = __ldg(&g_dt[o + di]);
            float scv = __ldg(&g_sc[o + di]);
            float zgv = __ldg(&g_zg[o + di]);
            float4 Bq = __ldg(&B4[(o>>2) + sq]);
            float4 Cq = __ldg(&C4[(o>>2) + sq]);
            float u = dtv * scv;
            h0 = fmaf(__expf(dtv*A[0]), h0, u*Bq.x);
            h1 = fmaf(__expf(dtv*A[1]), h1, u*Bq.y);
            h2 = fmaf(__expf(dtv*A[2]), h2, u*Bq.z);
            h3 = fmaf(__expf(dtv*A[3]), h3, u*Bq.w);
            float y = h0*Cq.x;
            y = fmaf(h1, Cq.y, y); y = fmaf(h2, Cq.z, y); y = fmaf(h3, Cq.w, y);
            y += __shfl_xor_sync(0xffffffffu, y, 1);
            y += __shfl_xor_sync(0xffffffffu, y, 2);
            if (sq == 0) g_yf[o + di] = fmaf(Dsk, scv, y) * zgv;
        }
    }
}

// ========== Kernel C: folded out_proj∘blk + partial time-pooling ==========
__global__ void __launch_bounds__(256) kC(
    const float* __restrict__ out_w, const float* __restrict__ blk_w,
    const float* __restrict__ blk_b)
{
    const int id = blockIdx.x*256 + threadIdx.x;
    const int n = id & 511, chunk = (id >> 9) & 15, c = id >> 13;
    const int tid = threadIdx.x;

    __shared__ float s_M[8][16];
    __shared__ float s_bb[8];
    if (tid < 128) {
        int d = tid >> 4, i = tid & 15;
        float m = 0.f;
        #pragma unroll
        for (int e = 0; e < 8; ++e)
            m = fmaf(blk_w[(c*8+d)*8+e], out_w[(c*8+e)*16+i], m);
        s_M[d][i] = m;
        if (i == 0) s_bb[d] = blk_b[c*8+d];
    }
    __syncthreads();

    float acc[8] = {0,0,0,0,0,0,0,0};
    const float4* Y4 = reinterpret_cast<const float4*>(g_yf);
    #pragma unroll 2
    for (int tt = 0; tt < 16; ++tt) {
        int t = chunk*16 + tt;
        int o = ((c*LF + t)*NN + n)*16;
        float4 a = __ldg(&Y4[(o>>2)+0]), b = __ldg(&Y4[(o>>2)+1]);
        float4 cc = __ldg(&Y4[(o>>2)+2]), dd = __ldg(&Y4[(o>>2)+3]);
        float y[16] = {a.x,a.y,a.z,a.w, b.x,b.y,b.z,b.w,
                       cc.x,cc.y,cc.z,cc.w, dd.x,dd.y,dd.z,dd.w};
        #pragma unroll
        for (int d = 0; d < 8; ++d) {
            float v = s_bb[d];
            #pragma unroll
            for (int i = 0; i < 16; ++i) v = fmaf(y[i], s_M[d][i], v);
            acc[d] += fsilu(v);
        }
    }
    #pragma unroll
    for (int d = 0; d < 8; ++d)
        g_part[((c*16 + chunk)*NN + n)*8 + d] = acc[d];
}

// ========== Kernel D: final pooling + LayerNorm(64) ==========
__global__ void __launch_bounds__(64) kD(
    const float* __restrict__ ln_g, const float* __restrict__ ln_b,
    float* __restrict__ out)
{
    const int n = blockIdx.x, f = threadIdx.x;
    const int c = f >> 3, d = f & 7;
    float s = 0.f;
    #pragma unroll
    for (int ch = 0; ch < 16; ++ch)
        s += g_part[((c*16 + ch)*NN + n)*8 + d];
    float feat = s * (1.0f/256.0f);

    __shared__ float buf[64];
    buf[f] = feat;
    __syncthreads();
    float s1 = 0.f, s2 = 0.f;
    #pragma unroll
    for (int i = 0; i < 64; ++i) { float v = buf[i]; s1 += v; s2 = fmaf(v, v, s2); }
    float mu  = s1 * (1.0f/64.0f);
    float var = fmaxf(s2 * (1.0f/64.0f) - mu*mu, 0.f);
    float inv = rsqrtf(var + 1e-5f);
    out[n*64 + f] = (feat - mu) * inv * ln_g[f] + ln_b[f];
}

extern "C" void kernel_launch(void* const* d_in, const int* in_sizes, int n_in,
                              void* d_out, int out_size) {
    const float* x      = (const float*)d_in[0];
    const float* lift_w = (const float*)d_in[1];
    const float* lift_b = (const float*)d_in[2];
    const float* ipw    = (const float*)d_in[3];
    const float* conv_w = (const float*)d_in[4];
    const float* conv_b = (const float*)d_in[5];
    const float* xpw    = (const float*)d_in[6];
    const float* dt_w   = (const float*)d_in[7];
    const float* dt_b   = (const float*)d_in[8];
    const float* A_log  = (const float*)d_in[9];
    const float* D_skip = (const float*)d_in[10];
    const float* out_w  = (const float*)d_in[11];
    const float* blk_w  = (const float*)d_in[12];
    const float* blk_b  = (const float*)d_in[13];
    const float* ln_g   = (const float*)d_in[14];
    const float* ln_b   = (const float*)d_in[15];
    float* out = (float*)d_out;

    kA<<<dim3(LF, NC), 256>>>(x, lift_w, lift_b, ipw, conv_w, conv_b, xpw, dt_w, dt_b);
    kB<<<1024, 256>>>(A_log, D_skip);
    kC<<<256, 256>>>(out_w, blk_w, blk_b);
    kD<<<NN, 64>>>(ln_g, ln_b, out);
}